// round 1
// baseline (speedup 1.0000x reference)
#include <cuda_runtime.h>
#include <math.h>

#define NN   100000   // NU == NI == 100000
#define HH   3
#define DD   32
#define HD   96       // H*D
#define SLOPE 0.01f

// ---------------- scratch (device globals; no allocation allowed) ----------------
__device__ float    g_FS [NN * HD];   // source projection (fs)
__device__ float    g_EL [NN * 3];    // attention left  scores per src node
__device__ float    g_ER [NN * 3];    // attention right scores per dst node
__device__ float    g_RES[NN * HD];   // residual projection of dst
__device__ float    g_ACC[NN * HD];   // unnormalized weighted message sum
__device__ float    g_DEN[NN * 3];    // softmax denominator per (dst, head)
__device__ unsigned g_M  [NN * 3];    // encoded running max per (dst, head)
__device__ float    g_GU [NN * HD];   // GAT output, user side
__device__ float    g_GI [NN * HD];   // GAT output, item side
__device__ float    g_HU [NN * DD];   // post-MLP user features (layer1)
__device__ float    g_HI [NN * DD];   // post-MLP item features (layer1)

// --------- order-preserving float <-> uint encoding for atomicMax on floats ---------
__device__ __forceinline__ unsigned enc_f(float f) {
    unsigned u = __float_as_uint(f);
    return (u & 0x80000000u) ? ~u : (u | 0x80000000u);
}
__device__ __forceinline__ float dec_f(unsigned u) {
    return (u & 0x80000000u) ? __uint_as_float(u & 0x7FFFFFFFu)
                             : __uint_as_float(~u);
}

// --------- vectorized global reduction (sm_90+) ---------
__device__ __forceinline__ void red_add_v4(float* addr, float a, float b, float c, float d) {
    asm volatile("red.global.add.v4.f32 [%0], {%1, %2, %3, %4};"
                 :: "l"(__cvta_generic_to_global(addr)), "f"(a), "f"(b), "f"(c), "f"(d)
                 : "memory");
}

// ---------------- GEMM: out[N,96] = X[N,K] @ W[K,96] ----------------
// block = (24,8) = 192 threads, tile = 32 rows x 96 cols, thread = 4 rows x 4 cols
template <int K>
__global__ void gemm96_kernel(const float* __restrict__ X, const float* __restrict__ W,
                              float* __restrict__ out, int N) {
    __shared__ __align__(16) float sW[K * 96];
    __shared__ float sX[32 * (K + 1)];
    const int t = threadIdx.y * 24 + threadIdx.x;
    const int row0 = blockIdx.x * 32;

    for (int i = t; i < K * 96; i += 192) sW[i] = W[i];
    for (int i = t; i < 32 * K; i += 192) {
        int r = i / K, k = i - r * K;
        int gr = row0 + r;
        sX[r * (K + 1) + k] = (gr < N) ? X[gr * K + k] : 0.f;
    }
    __syncthreads();

    const int cg = threadIdx.x;       // 0..23 (col group of 4)
    const int rg = threadIdx.y;       // 0..7  (row group of 4)
    float acc[4][4] = {};
    #pragma unroll
    for (int k = 0; k < K; k++) {
        float4 w = *reinterpret_cast<const float4*>(&sW[k * 96 + cg * 4]);
        #pragma unroll
        for (int r = 0; r < 4; r++) {
            float xv = sX[(rg * 4 + r) * (K + 1) + k];
            acc[r][0] += xv * w.x; acc[r][1] += xv * w.y;
            acc[r][2] += xv * w.z; acc[r][3] += xv * w.w;
        }
    }
    #pragma unroll
    for (int r = 0; r < 4; r++) {
        int gr = row0 + rg * 4 + r;
        if (gr < N)
            *reinterpret_cast<float4*>(&out[gr * 96 + cg * 4]) =
                make_float4(acc[r][0], acc[r][1], acc[r][2], acc[r][3]);
    }
}

// ---------------- attn score: out[n,h] = sum_k X[n,k] * (sum_d W[k,h*32+d]*a[h*32+d]) ----------------
template <int K>
__global__ void attnvec_kernel(const float* __restrict__ X, const float* __restrict__ W,
                               const float* __restrict__ a, float* __restrict__ out, int N) {
    __shared__ float wr[K * 3];
    __shared__ float sX[128 * (K + 1)];
    const int t = threadIdx.x;  // 128 threads

    for (int i = t; i < K * 3; i += 128) {
        int k = i / 3, h = i - k * 3;
        float s = 0.f;
        #pragma unroll
        for (int d = 0; d < 32; d++) s += W[k * 96 + h * 32 + d] * a[h * 32 + d];
        wr[i] = s;
    }
    const int n0 = blockIdx.x * 128;
    for (int i = t; i < 128 * K; i += 128) {
        int r = i / K, k = i - r * K;
        int gn = n0 + r;
        sX[r * (K + 1) + k] = (gn < N) ? X[gn * K + k] : 0.f;
    }
    __syncthreads();

    int n = n0 + t;
    if (n >= N) return;
    float a0 = 0.f, a1 = 0.f, a2 = 0.f;
    #pragma unroll
    for (int k = 0; k < K; k++) {
        float xv = sX[t * (K + 1) + k];
        a0 += xv * wr[k * 3 + 0];
        a1 += xv * wr[k * 3 + 1];
        a2 += xv * wr[k * 3 + 2];
    }
    out[n * 3 + 0] = a0; out[n * 3 + 1] = a1; out[n * 3 + 2] = a2;
}

// ---------------- reset accumulators ----------------
__global__ void reset_kernel(float* acc, float* den, unsigned* m, int n) {
    int i = blockIdx.x * blockDim.x + threadIdx.x;
    if (i < n * HD) acc[i] = 0.f;
    if (i < n * 3) { den[i] = 0.f; m[i] = 0u; }
}

// ---------------- edge pass 1: per-destination max of leaky(el+er) ----------------
__global__ void edge_max_kernel(const int* __restrict__ src, const int* __restrict__ dst,
                                const float* __restrict__ el, const float* __restrict__ er,
                                unsigned* __restrict__ m, int ne) {
    int e = blockIdx.x * blockDim.x + threadIdx.x;
    if (e >= ne) return;
    int s = src[e], d = dst[e];
    #pragma unroll
    for (int h = 0; h < 3; h++) {
        float v = el[s * 3 + h] + er[d * 3 + h];
        v = v > 0.f ? v : SLOPE * v;
        atomicMax(&m[d * 3 + h], enc_f(v));
    }
}

// ---------------- edge pass 2: exp, denominator, weighted message reduction ----------------
__global__ void edge_acc_kernel(const int* __restrict__ src, const int* __restrict__ dst,
                                const float* __restrict__ el, const float* __restrict__ er,
                                const unsigned* __restrict__ m, const float* __restrict__ fs,
                                float* __restrict__ den, float* __restrict__ acc, int ne) {
    int idx = blockIdx.x * blockDim.x + threadIdx.x;
    if (idx >= ne * 3) return;
    int e = idx / 3, h = idx - e * 3;
    int s = src[e], d = dst[e];
    float v = el[s * 3 + h] + er[d * 3 + h];
    v = v > 0.f ? v : SLOPE * v;
    float mm = dec_f(m[d * 3 + h]);
    float ex = expf(v - mm);
    atomicAdd(&den[d * 3 + h], ex);
    const float4* f4 = reinterpret_cast<const float4*>(fs + (size_t)s * HD + h * 32);
    float* ab = acc + (size_t)d * HD + h * 32;
    #pragma unroll
    for (int i = 0; i < 8; i++) {
        float4 f = f4[i];
        red_add_v4(ab + i * 4, f.x * ex, f.y * ex, f.z * ex, f.w * ex);
    }
}

// ---------------- finalize: out = guard(acc/den) + res + bias ----------------
__global__ void finalize_kernel(const float* __restrict__ acc, const float* __restrict__ den,
                                const float* __restrict__ res, const float* __restrict__ bias,
                                float* __restrict__ out, int n) {
    int i = blockIdx.x * blockDim.x + threadIdx.x;
    if (i >= n * HD) return;
    int node = i / HD, j = i - node * HD, h = j >> 5;
    float dv = den[node * 3 + h];
    float r = dv > 0.f ? acc[i] / dv : 0.f;
    out[i] = r + res[i] + bias[j];
}

// ---------------- Linear(96->32) + BatchNorm(eval) + ReLU ----------------
// block = 256 = 8 nodes x 32 cols
__global__ void lin_bn_relu_kernel(const float* __restrict__ in, const float* __restrict__ W,
                                   const float* __restrict__ b, const float* __restrict__ bn,
                                   float* __restrict__ out, int n) {
    __shared__ float sW[96 * 32];
    __shared__ float sIn[8][97];
    __shared__ float sScale[32], sShift[32];
    const int t = threadIdx.x;

    for (int i = t; i < 96 * 32; i += 256) sW[i] = W[i];
    if (t < 32) {
        float gamma = bn[t], beta = bn[32 + t], mean = bn[64 + t], var = bn[96 + t];
        float sc = gamma * rsqrtf(var + 1e-5f);
        sScale[t] = sc;
        sShift[t] = beta + (b[t] - mean) * sc;
    }
    const int node0 = blockIdx.x * 8;
    for (int i = t; i < 8 * 96; i += 256) {
        int r = i / 96, k = i - r * 96;
        int gn = node0 + r;
        sIn[r][k] = (gn < n) ? in[(size_t)gn * 96 + k] : 0.f;
    }
    __syncthreads();

    int r = t >> 5, c = t & 31;
    int gn = node0 + r;
    if (gn >= n) return;
    float acc = 0.f;
    #pragma unroll
    for (int k = 0; k < 96; k++) acc += sIn[r][k] * sW[k * 32 + c];
    float y = acc * sScale[c] + sShift[c];
    out[(size_t)gn * 32 + c] = y > 0.f ? y : 0.f;
}

// ==================================================================================
extern "C" void kernel_launch(void* const* d_in, const int* in_sizes, int n_in,
                              void* d_out, int out_size) {
    const float* emb_user = (const float*)d_in[0];
    const float* emb_item = (const float*)d_in[1];
    const float* W1    = (const float*)d_in[2];
    const float* attn1 = (const float*)d_in[3];
    const float* res1  = (const float*)d_in[4];
    const float* bias1 = (const float*)d_in[5];
    const float* nnW1  = (const float*)d_in[6];
    const float* nnb1  = (const float*)d_in[7];
    const float* bn1   = (const float*)d_in[8];
    const float* W2    = (const float*)d_in[9];
    const float* attn2 = (const float*)d_in[10];
    const float* res2  = (const float*)d_in[11];
    const float* bias2 = (const float*)d_in[12];
    const float* nnW2  = (const float*)d_in[13];
    const float* nnb2  = (const float*)d_in[14];
    const float* bn2   = (const float*)d_in[15];
    const int* go_src   = (const int*)d_in[16];
    const int* go_dst   = (const int*)d_in[17];
    const int* back_src = (const int*)d_in[18];
    const int* back_dst = (const int*)d_in[19];
    const int E = in_sizes[16];
    const int N = NN;

    float *FS, *EL, *ER, *RES, *ACC, *DEN, *GU, *GI, *HU, *HI; unsigned* M;
    cudaGetSymbolAddress((void**)&FS,  g_FS);
    cudaGetSymbolAddress((void**)&EL,  g_EL);
    cudaGetSymbolAddress((void**)&ER,  g_ER);
    cudaGetSymbolAddress((void**)&RES, g_RES);
    cudaGetSymbolAddress((void**)&ACC, g_ACC);
    cudaGetSymbolAddress((void**)&DEN, g_DEN);
    cudaGetSymbolAddress((void**)&M,   g_M);
    cudaGetSymbolAddress((void**)&GU,  g_GU);
    cudaGetSymbolAddress((void**)&GI,  g_GI);
    cudaGetSymbolAddress((void**)&HU,  g_HU);
    cudaGetSymbolAddress((void**)&HI,  g_HI);

    const dim3 gb(24, 8);
    const int gemmBlocks = (N + 31) / 32;
    const int nodeBlocks96 = (N * HD + 255) / 256;

    auto gat_pass = [&](const float* Xs, const float* Xd, int K,
                        const float* W, const float* al, const float* ar,
                        const float* rW, const float* bias,
                        const int* src, const int* dst, float* gout) {
        if (K == 64) {
            gemm96_kernel<64><<<gemmBlocks, gb>>>(Xs, W, FS, N);
            attnvec_kernel<64><<<(N + 127) / 128, 128>>>(Xs, W, al, EL, N);
            attnvec_kernel<64><<<(N + 127) / 128, 128>>>(Xd, W, ar, ER, N);
            gemm96_kernel<64><<<gemmBlocks, gb>>>(Xd, rW, RES, N);
        } else {
            gemm96_kernel<32><<<gemmBlocks, gb>>>(Xs, W, FS, N);
            attnvec_kernel<32><<<(N + 127) / 128, 128>>>(Xs, W, al, EL, N);
            attnvec_kernel<32><<<(N + 127) / 128, 128>>>(Xd, W, ar, ER, N);
            gemm96_kernel<32><<<gemmBlocks, gb>>>(Xd, rW, RES, N);
        }
        reset_kernel<<<nodeBlocks96, 256>>>(ACC, DEN, M, N);
        edge_max_kernel<<<(E + 255) / 256, 256>>>(src, dst, EL, ER, M, E);
        edge_acc_kernel<<<(E * 3 + 255) / 256, 256>>>(src, dst, EL, ER, M, FS, DEN, ACC, E);
        finalize_kernel<<<nodeBlocks96, 256>>>(ACC, DEN, RES, bias, gout, N);
    };

    // ---- layer 1 ----
    // 'go' : user -> item  (rel 0)
    gat_pass(emb_user, emb_item, 64, W1, attn1, attn1 + 96, res1, bias1,
             go_src, go_dst, GI);
    // 'back' : item -> user (rel 1)
    gat_pass(emb_item, emb_user, 64, W1 + 64 * 96, attn1 + 192, attn1 + 288,
             res1 + 64 * 96, bias1 + 96, back_src, back_dst, GU);
    lin_bn_relu_kernel<<<(N + 7) / 8, 256>>>(GU, nnW1, nnb1, bn1, HU, N);              // user = type 0
    lin_bn_relu_kernel<<<(N + 7) / 8, 256>>>(GI, nnW1 + 96 * 32, nnb1 + 32, bn1 + 128, HI, N); // item = type 1

    // ---- layer 2 ----
    gat_pass(HU, HI, 32, W2, attn2, attn2 + 96, res2, bias2, go_src, go_dst, GI);
    gat_pass(HI, HU, 32, W2 + 32 * 96, attn2 + 192, attn2 + 288,
             res2 + 32 * 96, bias2 + 96, back_src, back_dst, GU);

    float* out = (float*)d_out;
    lin_bn_relu_kernel<<<(N + 7) / 8, 256>>>(GU, nnW2, nnb2, bn2, out, N);                        // h_user2
    lin_bn_relu_kernel<<<(N + 7) / 8, 256>>>(GI, nnW2 + 96 * 32, nnb2 + 32, bn2 + 128, out + (size_t)N * 32, N); // h_item2
}

// round 2
// speedup vs baseline: 1.6699x; 1.6699x over previous
#include <cuda_runtime.h>
#include <math.h>

#define NN   100000
#define HD   96
#define SLOPE 0.01f
typedef unsigned long long ull;

// ---------------- scratch ----------------
__device__ float g_FS [NN * HD];
__device__ float g_EL [NN * 3];
__device__ float g_ER [NN * 3];
__device__ float g_RES[NN * HD];
__device__ float g_GU [NN * HD];
__device__ float g_GI [NN * HD];
__device__ float g_HU [NN * 32];
__device__ float g_HI [NN * 32];
// CSR (2 relations: 0=go dst=item, 1=back dst=user)
__device__ int g_deg [2 * NN];
__device__ int g_off [2 * NN];
__device__ int g_cur [2 * NN];
__device__ int g_eidx[2 * 500000];
__device__ int g_bsum[2 * 128];

// ---------------- f32x2 helpers ----------------
__device__ __forceinline__ ull pack2(float x, float y) {
    ull r; asm("mov.b64 %0, {%1, %2};" : "=l"(r) : "f"(x), "f"(y)); return r;
}
__device__ __forceinline__ void ffma2(ull& d, ull a, ull b) {
    asm("fma.rn.f32x2 %0, %1, %2, %0;" : "+l"(d) : "l"(a), "l"(b));
}
__device__ __forceinline__ void unpack2(float& x, float& y, ull v) {
    asm("mov.b64 {%0, %1}, %2;" : "=f"(x), "=f"(y) : "l"(v));
}

// ---------------- GEMM: out[N,96] = X[N,K] @ W[K,96], f32x2 over row pairs ----------------
// block (24,8)=192 threads; tile 64 rows x 96 cols; thread: 4 row-pairs x 4 cols
template <int K>
__global__ void gemm96_kernel(const float* __restrict__ X, const float* __restrict__ W,
                              float* __restrict__ out, int N) {
    __shared__ __align__(16) float sW[K * 96];
    __shared__ __align__(8) ull sXp[K][33];          // [k][rowpair], padded
    const int t = threadIdx.y * 24 + threadIdx.x;
    const int row0 = blockIdx.x * 64;

    for (int i = t; i < K * 96; i += 192) sW[i] = W[i];
    float* sXf = (float*)sXp;                         // float view: index k*66 + r
    for (int i = t; i < 64 * K; i += 192) {
        int r = i / K, k = i - r * K;                 // k fastest -> coalesced global
        int gr = row0 + r;
        sXf[k * 66 + r] = (gr < N) ? X[(size_t)gr * K + k] : 0.f;
    }
    __syncthreads();

    const int cg = threadIdx.x;   // col group (4 cols)
    const int rg = threadIdx.y;   // 4 row-pairs
    ull acc[4][4];
    #pragma unroll
    for (int a = 0; a < 4; a++)
        #pragma unroll
        for (int b = 0; b < 4; b++) acc[a][b] = 0ull;

    #pragma unroll 8
    for (int k = 0; k < K; k++) {
        float4 w = *reinterpret_cast<const float4*>(&sW[k * 96 + cg * 4]);
        ull w0 = pack2(w.x, w.x), w1 = pack2(w.y, w.y);
        ull w2 = pack2(w.z, w.z), w3 = pack2(w.w, w.w);
        #pragma unroll
        for (int rp = 0; rp < 4; rp++) {
            ull xp = sXp[k][rg * 4 + rp];
            ffma2(acc[rp][0], xp, w0);
            ffma2(acc[rp][1], xp, w1);
            ffma2(acc[rp][2], xp, w2);
            ffma2(acc[rp][3], xp, w3);
        }
    }
    #pragma unroll
    for (int rp = 0; rp < 4; rp++) {
        int row = row0 + (rg * 4 + rp) * 2;
        float lo0, hi0, lo1, hi1, lo2, hi2, lo3, hi3;
        unpack2(lo0, hi0, acc[rp][0]); unpack2(lo1, hi1, acc[rp][1]);
        unpack2(lo2, hi2, acc[rp][2]); unpack2(lo3, hi3, acc[rp][3]);
        if (row < N)
            *reinterpret_cast<float4*>(&out[(size_t)row * 96 + cg * 4]) =
                make_float4(lo0, lo1, lo2, lo3);
        if (row + 1 < N)
            *reinterpret_cast<float4*>(&out[(size_t)(row + 1) * 96 + cg * 4]) =
                make_float4(hi0, hi1, hi2, hi3);
    }
}

// ---------------- attn score: out[n,h] = X[n,:] . (W @ a_h) ----------------
template <int K>
__global__ void attnvec_kernel(const float* __restrict__ X, const float* __restrict__ W,
                               const float* __restrict__ a, float* __restrict__ out, int N) {
    __shared__ float wr[K * 3];
    __shared__ float sX[128 * (K + 1)];
    const int t = threadIdx.x;  // 128

    for (int i = t; i < K * 3; i += 128) {
        int k = i / 3, h = i - k * 3;
        float s = 0.f;
        #pragma unroll
        for (int d = 0; d < 32; d++) s += W[k * 96 + h * 32 + d] * a[h * 32 + d];
        wr[i] = s;
    }
    const int n0 = blockIdx.x * 128;
    for (int i = t; i < 128 * K; i += 128) {
        int r = i / K, k = i - r * K;
        int gn = n0 + r;
        sX[r * (K + 1) + k] = (gn < N) ? X[(size_t)gn * K + k] : 0.f;
    }
    __syncthreads();
    int n = n0 + t;
    if (n >= N) return;
    float a0 = 0.f, a1 = 0.f, a2 = 0.f;
    #pragma unroll
    for (int k = 0; k < K; k++) {
        float xv = sX[t * (K + 1) + k];
        a0 += xv * wr[k * 3 + 0];
        a1 += xv * wr[k * 3 + 1];
        a2 += xv * wr[k * 3 + 2];
    }
    out[n * 3 + 0] = a0; out[n * 3 + 1] = a1; out[n * 3 + 2] = a2;
}

// ---------------- CSR build ----------------
__global__ void zero_kernel(int* p, int n) {
    int i = blockIdx.x * blockDim.x + threadIdx.x;
    if (i < n) p[i] = 0;
}
__global__ void count_kernel(const int* __restrict__ dst, int* __restrict__ deg, int ne) {
    int e = blockIdx.x * blockDim.x + threadIdx.x;
    if (e < ne) atomicAdd(&deg[dst[e]], 1);
}
__global__ void scan1_kernel(const int* __restrict__ in, int* __restrict__ out,
                             int* __restrict__ bsum, int n) {
    __shared__ int sh[1024];
    int i = blockIdx.x * 1024 + threadIdx.x;
    int v = (i < n) ? in[i] : 0;
    sh[threadIdx.x] = v; __syncthreads();
    for (int ofs = 1; ofs < 1024; ofs <<= 1) {
        int tv = (threadIdx.x >= ofs) ? sh[threadIdx.x - ofs] : 0;
        __syncthreads();
        sh[threadIdx.x] += tv;
        __syncthreads();
    }
    if (i < n) out[i] = sh[threadIdx.x] - v;   // exclusive
    if (threadIdx.x == 1023) bsum[blockIdx.x] = sh[1023];
}
__global__ void scan2_kernel(int* bsum, int nb) {
    if (threadIdx.x == 0) {
        int run = 0;
        for (int b = 0; b < nb; b++) { int t = bsum[b]; bsum[b] = run; run += t; }
    }
}
__global__ void scan3_copy_kernel(int* __restrict__ off, const int* __restrict__ bsum,
                                  int* __restrict__ cur, int n) {
    int i = blockIdx.x * 1024 + threadIdx.x;
    if (i < n) { int v = off[i] + bsum[blockIdx.x]; off[i] = v; cur[i] = v; }
}
__global__ void scatter_kernel(const int* __restrict__ src, const int* __restrict__ dst,
                               int* __restrict__ cur, int* __restrict__ eidx, int ne) {
    int e = blockIdx.x * blockDim.x + threadIdx.x;
    if (e < ne) {
        int p = atomicAdd(&cur[dst[e]], 1);
        eidx[p] = src[e];
    }
}

// ---------------- fused GAT gather: warp per destination ----------------
__global__ void gat_gather_kernel(const int* __restrict__ eidx, const int* __restrict__ off,
                                  const float* __restrict__ el, const float* __restrict__ er,
                                  const float* __restrict__ fs, const float* __restrict__ res,
                                  const float* __restrict__ bias, float* __restrict__ out,
                                  int n, int ne) {
    int w = (blockIdx.x * blockDim.x + threadIdx.x) >> 5;
    int lane = threadIdx.x & 31;
    if (w >= n) return;
    int beg = off[w];
    int end = (w + 1 < n) ? off[w + 1] : ne;
    float er0 = er[w * 3], er1 = er[w * 3 + 1], er2 = er[w * 3 + 2];
    float a0 = 0.f, a1 = 0.f, a2 = 0.f, d0 = 0.f, d1 = 0.f, d2 = 0.f;
    for (int p = beg; p < end; ++p) {
        int s = eidx[p];
        float v0 = el[s * 3] + er0;
        float v1 = el[s * 3 + 1] + er1;
        float v2 = el[s * 3 + 2] + er2;
        v0 = v0 > 0.f ? v0 : SLOPE * v0;
        v1 = v1 > 0.f ? v1 : SLOPE * v1;
        v2 = v2 > 0.f ? v2 : SLOPE * v2;
        float ex0 = __expf(v0), ex1 = __expf(v1), ex2 = __expf(v2);
        const float* fr = fs + (size_t)s * 96 + lane;
        a0 = fmaf(ex0, fr[0],  a0);
        a1 = fmaf(ex1, fr[32], a1);
        a2 = fmaf(ex2, fr[64], a2);
        d0 += ex0; d1 += ex1; d2 += ex2;
    }
    size_t o = (size_t)w * 96 + lane;
    out[o]      = (d0 > 0.f ? a0 / d0 : 0.f) + res[o]      + bias[lane];
    out[o + 32] = (d1 > 0.f ? a1 / d1 : 0.f) + res[o + 32] + bias[lane + 32];
    out[o + 64] = (d2 > 0.f ? a2 / d2 : 0.f) + res[o + 64] + bias[lane + 64];
}

// ---------------- Linear(96->32) + BN(eval) + ReLU: 4 nodes per thread ----------------
__global__ void lin_bn_relu_kernel(const float* __restrict__ in, const float* __restrict__ W,
                                   const float* __restrict__ b, const float* __restrict__ bn,
                                   float* __restrict__ out, int n) {
    __shared__ float sW[96 * 32];
    __shared__ float sIn[32][97];
    __shared__ float sScale[32], sShift[32];
    const int t = threadIdx.x;  // 256

    for (int i = t; i < 96 * 32; i += 256) sW[i] = W[i];
    if (t < 32) {
        float gamma = bn[t], beta = bn[32 + t], mean = bn[64 + t], var = bn[96 + t];
        float sc = gamma * rsqrtf(var + 1e-5f);
        sScale[t] = sc;
        sShift[t] = beta + (b[t] - mean) * sc;
    }
    const int node0 = blockIdx.x * 32;
    for (int i = t; i < 32 * 96; i += 256) {
        int r = i / 96, k = i - r * 96;
        int gn = node0 + r;
        sIn[r][k] = (gn < n) ? in[(size_t)gn * 96 + k] : 0.f;
    }
    __syncthreads();

    const int c = t & 31, ng = t >> 5;  // ng 0..7, 4 nodes each
    float acc[4] = {0.f, 0.f, 0.f, 0.f};
    #pragma unroll 8
    for (int k = 0; k < 96; k++) {
        float wv = sW[k * 32 + c];
        #pragma unroll
        for (int r = 0; r < 4; r++) acc[r] = fmaf(sIn[ng * 4 + r][k], wv, acc[r]);
    }
    #pragma unroll
    for (int r = 0; r < 4; r++) {
        int gn = node0 + ng * 4 + r;
        if (gn < n) {
            float y = acc[r] * sScale[c] + sShift[c];
            out[(size_t)gn * 32 + c] = y > 0.f ? y : 0.f;
        }
    }
}

// ==================================================================================
extern "C" void kernel_launch(void* const* d_in, const int* in_sizes, int n_in,
                              void* d_out, int out_size) {
    const float* emb_user = (const float*)d_in[0];
    const float* emb_item = (const float*)d_in[1];
    const float* W1    = (const float*)d_in[2];
    const float* attn1 = (const float*)d_in[3];
    const float* res1  = (const float*)d_in[4];
    const float* bias1 = (const float*)d_in[5];
    const float* nnW1  = (const float*)d_in[6];
    const float* nnb1  = (const float*)d_in[7];
    const float* bn1   = (const float*)d_in[8];
    const float* W2    = (const float*)d_in[9];
    const float* attn2 = (const float*)d_in[10];
    const float* res2  = (const float*)d_in[11];
    const float* bias2 = (const float*)d_in[12];
    const float* nnW2  = (const float*)d_in[13];
    const float* nnb2  = (const float*)d_in[14];
    const float* bn2   = (const float*)d_in[15];
    const int* go_src   = (const int*)d_in[16];
    const int* go_dst   = (const int*)d_in[17];
    const int* back_src = (const int*)d_in[18];
    const int* back_dst = (const int*)d_in[19];
    const int E = in_sizes[16];
    const int N = NN;

    float *FS, *EL, *ER, *RES, *GU, *GI, *HU, *HI;
    int *DEG, *OFF, *CUR, *EIDX, *BSUM;
    cudaGetSymbolAddress((void**)&FS,   g_FS);
    cudaGetSymbolAddress((void**)&EL,   g_EL);
    cudaGetSymbolAddress((void**)&ER,   g_ER);
    cudaGetSymbolAddress((void**)&RES,  g_RES);
    cudaGetSymbolAddress((void**)&GU,   g_GU);
    cudaGetSymbolAddress((void**)&GI,   g_GI);
    cudaGetSymbolAddress((void**)&HU,   g_HU);
    cudaGetSymbolAddress((void**)&HI,   g_HI);
    cudaGetSymbolAddress((void**)&DEG,  g_deg);
    cudaGetSymbolAddress((void**)&OFF,  g_off);
    cudaGetSymbolAddress((void**)&CUR,  g_cur);
    cudaGetSymbolAddress((void**)&EIDX, g_eidx);
    cudaGetSymbolAddress((void**)&BSUM, g_bsum);

    const int NB = (N + 1023) / 1024;          // 98 scan blocks
    const int eb = (E + 255) / 256;

    // ---- CSR build (once, reused by both layers) ----
    zero_kernel<<<(2 * N + 255) / 256, 256>>>(DEG, 2 * N);
    count_kernel<<<eb, 256>>>(go_dst,   DEG,     E);   // rel 0 -> item dsts
    count_kernel<<<eb, 256>>>(back_dst, DEG + N, E);   // rel 1 -> user dsts
    for (int r = 0; r < 2; r++) {
        scan1_kernel<<<NB, 1024>>>(DEG + r * N, OFF + r * N, BSUM + r * 128, N);
        scan2_kernel<<<1, 32>>>(BSUM + r * 128, NB);
        scan3_copy_kernel<<<NB, 1024>>>(OFF + r * N, BSUM + r * 128, CUR + r * N, N);
    }
    scatter_kernel<<<eb, 256>>>(go_src,   go_dst,   CUR,     EIDX,     E);
    scatter_kernel<<<eb, 256>>>(back_src, back_dst, CUR + N, EIDX + E, E);

    const int gemmBlocks = (N + 63) / 64;
    const int gatherBlocks = (N * 32 + 255) / 256;   // warp per dst

    auto gat_pass = [&](const float* Xs, const float* Xd, int K,
                        const float* W, const float* al, const float* ar,
                        const float* rW, const float* bias,
                        const int* eidx, const int* off, float* gout) {
        if (K == 64) {
            gemm96_kernel<64><<<gemmBlocks, dim3(24, 8)>>>(Xs, W, FS, N);
            attnvec_kernel<64><<<(N + 127) / 128, 128>>>(Xs, W, al, EL, N);
            attnvec_kernel<64><<<(N + 127) / 128, 128>>>(Xd, W, ar, ER, N);
            gemm96_kernel<64><<<gemmBlocks, dim3(24, 8)>>>(Xd, rW, RES, N);
        } else {
            gemm96_kernel<32><<<gemmBlocks, dim3(24, 8)>>>(Xs, W, FS, N);
            attnvec_kernel<32><<<(N + 127) / 128, 128>>>(Xs, W, al, EL, N);
            attnvec_kernel<32><<<(N + 127) / 128, 128>>>(Xd, W, ar, ER, N);
            gemm96_kernel<32><<<gemmBlocks, dim3(24, 8)>>>(Xd, rW, RES, N);
        }
        gat_gather_kernel<<<gatherBlocks, 256>>>(eidx, off, EL, ER, FS, RES, bias, gout, N, E);
    };

    // ---- layer 1 ----
    gat_pass(emb_user, emb_item, 64, W1, attn1, attn1 + 96, res1, bias1,
             EIDX, OFF, GI);                                    // go: user->item
    gat_pass(emb_item, emb_user, 64, W1 + 64 * 96, attn1 + 192, attn1 + 288,
             res1 + 64 * 96, bias1 + 96, EIDX + E, OFF + N, GU); // back: item->user
    lin_bn_relu_kernel<<<(N + 31) / 32, 256>>>(GU, nnW1, nnb1, bn1, HU, N);
    lin_bn_relu_kernel<<<(N + 31) / 32, 256>>>(GI, nnW1 + 96 * 32, nnb1 + 32, bn1 + 128, HI, N);

    // ---- layer 2 ----
    gat_pass(HU, HI, 32, W2, attn2, attn2 + 96, res2, bias2, EIDX, OFF, GI);
    gat_pass(HI, HU, 32, W2 + 32 * 96, attn2 + 192, attn2 + 288,
             res2 + 32 * 96, bias2 + 96, EIDX + E, OFF + N, GU);

    float* out = (float*)d_out;
    lin_bn_relu_kernel<<<(N + 31) / 32, 256>>>(GU, nnW2, nnb2, bn2, out, N);
    lin_bn_relu_kernel<<<(N + 31) / 32, 256>>>(GI, nnW2 + 96 * 32, nnb2 + 32, bn2 + 128,
                                               out + (size_t)N * 32, N);
}

// round 3
// speedup vs baseline: 1.8516x; 1.1088x over previous
#include <cuda_runtime.h>
#include <math.h>

#define NN   100000
#define EE   500000
#define HD   96
#define SLOPE 0.01f
typedef unsigned long long ull;

// ---------------- scratch ----------------
__device__ float g_FS [NN * HD];
__device__ float g_EL [NN * 3];
__device__ float g_ER [NN * 3];
__device__ float g_RES[NN * HD];
__device__ float g_GU [NN * HD];
__device__ float g_GI [NN * HD];
__device__ float g_HU [NN * 32];
__device__ float g_HI [NN * 32];
__device__ float g_EX [2 * EE * 3];
// CSR (joint over 2 relations: 0=go dst=item, 1=back dst=user)
__device__ int g_deg [2 * NN];
__device__ int g_off [2 * NN];
__device__ int g_cur [2 * NN];
__device__ int g_eidx[2 * EE];
__device__ int g_edst[2 * EE];
__device__ int g_bsum[256];

// ---------------- f32x2 helpers ----------------
__device__ __forceinline__ ull pack2(float x, float y) {
    ull r; asm("mov.b64 %0, {%1, %2};" : "=l"(r) : "f"(x), "f"(y)); return r;
}
__device__ __forceinline__ void ffma2(ull& d, ull a, ull b) {
    asm("fma.rn.f32x2 %0, %1, %2, %0;" : "+l"(d) : "l"(a), "l"(b));
}
__device__ __forceinline__ void unpack2(float& x, float& y, ull v) {
    asm("mov.b64 {%0, %1}, %2;" : "=f"(x), "=f"(y) : "l"(v));
}

// ---------------- dual GEMM: y=0:(X0,W0)->O0  y=1:(X1,W1)->O1 ----------------
// out[N,96] = X[N,K] @ W[K,96]; block (24,8); tile 64 rows; f32x2 row pairs
template <int K>
__global__ void gemm96_dual_kernel(const float* __restrict__ X0, const float* __restrict__ W0,
                                   float* __restrict__ O0,
                                   const float* __restrict__ X1, const float* __restrict__ W1,
                                   float* __restrict__ O1, int N) {
    const float* X = blockIdx.y ? X1 : X0;
    const float* W = blockIdx.y ? W1 : W0;
    float*       O = blockIdx.y ? O1 : O0;

    __shared__ __align__(16) float sW[K * 96];
    __shared__ __align__(8) ull sXp[K][33];
    const int t = threadIdx.y * 24 + threadIdx.x;
    const int row0 = blockIdx.x * 64;

    for (int i = t; i < K * 96; i += 192) sW[i] = W[i];
    float* sXf = (float*)sXp;
    for (int i = t; i < 64 * K; i += 192) {
        int r = i / K, k = i - r * K;
        int gr = row0 + r;
        sXf[k * 66 + r] = (gr < N) ? X[(size_t)gr * K + k] : 0.f;
    }
    __syncthreads();

    const int cg = threadIdx.x;
    const int rg = threadIdx.y;
    ull acc[4][4];
    #pragma unroll
    for (int a = 0; a < 4; a++)
        #pragma unroll
        for (int b = 0; b < 4; b++) acc[a][b] = 0ull;

    #pragma unroll 8
    for (int k = 0; k < K; k++) {
        float4 w = *reinterpret_cast<const float4*>(&sW[k * 96 + cg * 4]);
        ull w0 = pack2(w.x, w.x), w1 = pack2(w.y, w.y);
        ull w2 = pack2(w.z, w.z), w3 = pack2(w.w, w.w);
        #pragma unroll
        for (int rp = 0; rp < 4; rp++) {
            ull xp = sXp[k][rg * 4 + rp];
            ffma2(acc[rp][0], xp, w0);
            ffma2(acc[rp][1], xp, w1);
            ffma2(acc[rp][2], xp, w2);
            ffma2(acc[rp][3], xp, w3);
        }
    }
    #pragma unroll
    for (int rp = 0; rp < 4; rp++) {
        int row = row0 + (rg * 4 + rp) * 2;
        float lo0, hi0, lo1, hi1, lo2, hi2, lo3, hi3;
        unpack2(lo0, hi0, acc[rp][0]); unpack2(lo1, hi1, acc[rp][1]);
        unpack2(lo2, hi2, acc[rp][2]); unpack2(lo3, hi3, acc[rp][3]);
        if (row < N)
            *reinterpret_cast<float4*>(&O[(size_t)row * 96 + cg * 4]) =
                make_float4(lo0, lo1, lo2, lo3);
        if (row + 1 < N)
            *reinterpret_cast<float4*>(&O[(size_t)(row + 1) * 96 + cg * 4]) =
                make_float4(hi0, hi1, hi2, hi3);
    }
}

// ---------------- dual attn score: y=0:(Xs,al)->EL  y=1:(Xd,ar)->ER ----------------
template <int K>
__global__ void attnvec_dual_kernel(const float* __restrict__ Xs, const float* __restrict__ Xd,
                                    const float* __restrict__ W,
                                    const float* __restrict__ al, const float* __restrict__ ar,
                                    float* __restrict__ EL, float* __restrict__ ER, int N) {
    const float* X = blockIdx.y ? Xd : Xs;
    const float* a = blockIdx.y ? ar : al;
    float*     out = blockIdx.y ? ER : EL;

    __shared__ float wr[K * 3];
    __shared__ float sX[128 * (K + 1)];
    const int t = threadIdx.x;  // 128

    for (int i = t; i < K * 3; i += 128) {
        int k = i / 3, h = i - k * 3;
        float s = 0.f;
        #pragma unroll
        for (int d = 0; d < 32; d++) s += W[k * 96 + h * 32 + d] * a[h * 32 + d];
        wr[i] = s;
    }
    const int n0 = blockIdx.x * 128;
    for (int i = t; i < 128 * K; i += 128) {
        int r = i / K, k = i - r * K;
        int gn = n0 + r;
        sX[r * (K + 1) + k] = (gn < N) ? X[(size_t)gn * K + k] : 0.f;
    }
    __syncthreads();
    int n = n0 + t;
    if (n >= N) return;
    float a0 = 0.f, a1 = 0.f, a2 = 0.f;
    #pragma unroll
    for (int k = 0; k < K; k++) {
        float xv = sX[t * (K + 1) + k];
        a0 += xv * wr[k * 3 + 0];
        a1 += xv * wr[k * 3 + 1];
        a2 += xv * wr[k * 3 + 2];
    }
    out[n * 3 + 0] = a0; out[n * 3 + 1] = a1; out[n * 3 + 2] = a2;
}

// ---------------- CSR build ----------------
__global__ void zero_kernel(int* p, int n) {
    int i = blockIdx.x * blockDim.x + threadIdx.x;
    if (i < n) p[i] = 0;
}
__global__ void count_dual_kernel(const int* __restrict__ d0, const int* __restrict__ d1,
                                  int* __restrict__ deg, int ne) {
    int e = blockIdx.x * blockDim.x + threadIdx.x;
    if (e >= ne) return;
    if (blockIdx.y == 0) atomicAdd(&deg[d0[e]], 1);
    else                 atomicAdd(&deg[NN + d1[e]], 1);
}
__global__ void scan1_kernel(const int* __restrict__ in, int* __restrict__ out,
                             int* __restrict__ bsum, int n) {
    __shared__ int sh[1024];
    int i = blockIdx.x * 1024 + threadIdx.x;
    int v = (i < n) ? in[i] : 0;
    sh[threadIdx.x] = v; __syncthreads();
    for (int ofs = 1; ofs < 1024; ofs <<= 1) {
        int tv = (threadIdx.x >= ofs) ? sh[threadIdx.x - ofs] : 0;
        __syncthreads();
        sh[threadIdx.x] += tv;
        __syncthreads();
    }
    if (i < n) out[i] = sh[threadIdx.x] - v;   // exclusive
    if (threadIdx.x == 1023) bsum[blockIdx.x] = sh[1023];
}
__global__ void scan2_kernel(int* bsum, int nb) {   // block scan, nb <= 256
    __shared__ int sh[256];
    int t = threadIdx.x;
    int v = (t < nb) ? bsum[t] : 0;
    sh[t] = v; __syncthreads();
    for (int ofs = 1; ofs < 256; ofs <<= 1) {
        int tv = (t >= ofs) ? sh[t - ofs] : 0;
        __syncthreads();
        sh[t] += tv;
        __syncthreads();
    }
    if (t < nb) bsum[t] = sh[t] - v;   // exclusive
}
__global__ void scan3_copy_kernel(int* __restrict__ off, const int* __restrict__ bsum,
                                  int* __restrict__ cur, int n) {
    int i = blockIdx.x * 1024 + threadIdx.x;
    if (i < n) { int v = off[i] + bsum[blockIdx.x]; off[i] = v; cur[i] = v; }
}
__global__ void scatter_dual_kernel(const int* __restrict__ s0, const int* __restrict__ d0,
                                    const int* __restrict__ s1, const int* __restrict__ d1,
                                    int* __restrict__ cur, int* __restrict__ eidx,
                                    int* __restrict__ edst, int ne) {
    int e = blockIdx.x * blockDim.x + threadIdx.x;
    if (e >= ne) return;
    int src, dst, base;
    if (blockIdx.y == 0) { src = s0[e]; dst = d0[e]; base = 0; }
    else                 { src = s1[e]; dst = d1[e]; base = NN; }
    int p = atomicAdd(&cur[base + dst], 1);
    eidx[p] = src;
    edst[p] = dst;
}

// ---------------- edge-parallel exp scores into CSR order ----------------
__global__ void edge_exp_kernel(const int* __restrict__ eidx, const int* __restrict__ edst,
                                const float* __restrict__ el, const float* __restrict__ er,
                                float* __restrict__ ex, int ne) {
    int i = blockIdx.x * blockDim.x + threadIdx.x;
    if (i >= ne) return;
    int s = eidx[i], d = edst[i];
    #pragma unroll
    for (int h = 0; h < 3; h++) {
        float v = el[s * 3 + h] + er[d * 3 + h];
        v = v > 0.f ? v : SLOPE * v;
        ex[i * 3 + h] = __expf(v);
    }
}

// ---------------- fused GAT gather: warp per destination, unroll x4 ----------------
__global__ void gat_gather_kernel(const int* __restrict__ eidx, const float* __restrict__ ex,
                                  const int* __restrict__ off,
                                  const float* __restrict__ fs, const float* __restrict__ res,
                                  const float* __restrict__ bias, float* __restrict__ out,
                                  int n, int rbase, int totalPos) {
    int w = (blockIdx.x * blockDim.x + threadIdx.x) >> 5;
    int lane = threadIdx.x & 31;
    if (w >= n) return;
    int gidx = rbase + w;
    int beg = off[gidx];
    int end = (gidx + 1 < 2 * NN) ? off[gidx + 1] : totalPos;

    float a0 = 0.f, a1 = 0.f, a2 = 0.f, d0 = 0.f, d1 = 0.f, d2 = 0.f;
    int p = beg;
    for (; p + 4 <= end; p += 4) {
        int s0 = eidx[p], s1 = eidx[p + 1], s2 = eidx[p + 2], s3 = eidx[p + 3];
        float e00 = ex[p * 3 + 0],  e01 = ex[p * 3 + 1],  e02 = ex[p * 3 + 2];
        float e10 = ex[p * 3 + 3],  e11 = ex[p * 3 + 4],  e12 = ex[p * 3 + 5];
        float e20 = ex[p * 3 + 6],  e21 = ex[p * 3 + 7],  e22 = ex[p * 3 + 8];
        float e30 = ex[p * 3 + 9],  e31 = ex[p * 3 + 10], e32 = ex[p * 3 + 11];
        const float* f0 = fs + (size_t)s0 * 96 + lane;
        const float* f1 = fs + (size_t)s1 * 96 + lane;
        const float* f2 = fs + (size_t)s2 * 96 + lane;
        const float* f3 = fs + (size_t)s3 * 96 + lane;
        float v00 = f0[0], v01 = f0[32], v02 = f0[64];
        float v10 = f1[0], v11 = f1[32], v12 = f1[64];
        float v20 = f2[0], v21 = f2[32], v22 = f2[64];
        float v30 = f3[0], v31 = f3[32], v32 = f3[64];
        a0 = fmaf(e00, v00, a0); a1 = fmaf(e01, v01, a1); a2 = fmaf(e02, v02, a2);
        a0 = fmaf(e10, v10, a0); a1 = fmaf(e11, v11, a1); a2 = fmaf(e12, v12, a2);
        a0 = fmaf(e20, v20, a0); a1 = fmaf(e21, v21, a1); a2 = fmaf(e22, v22, a2);
        a0 = fmaf(e30, v30, a0); a1 = fmaf(e31, v31, a1); a2 = fmaf(e32, v32, a2);
        d0 += (e00 + e10) + (e20 + e30);
        d1 += (e01 + e11) + (e21 + e31);
        d2 += (e02 + e12) + (e22 + e32);
    }
    for (; p < end; ++p) {
        int s = eidx[p];
        float e0 = ex[p * 3], e1 = ex[p * 3 + 1], e2 = ex[p * 3 + 2];
        const float* fr = fs + (size_t)s * 96 + lane;
        a0 = fmaf(e0, fr[0],  a0);
        a1 = fmaf(e1, fr[32], a1);
        a2 = fmaf(e2, fr[64], a2);
        d0 += e0; d1 += e1; d2 += e2;
    }
    size_t o = (size_t)w * 96 + lane;
    out[o]      = (d0 > 0.f ? a0 / d0 : 0.f) + res[o]      + bias[lane];
    out[o + 32] = (d1 > 0.f ? a1 / d1 : 0.f) + res[o + 32] + bias[lane + 32];
    out[o + 64] = (d2 > 0.f ? a2 / d2 : 0.f) + res[o + 64] + bias[lane + 64];
}

// ---------------- dual Linear(96->32) + BN(eval) + ReLU ----------------
__global__ void lin_bn_relu_dual_kernel(const float* __restrict__ in0, const float* __restrict__ in1,
                                        const float* __restrict__ Wb, const float* __restrict__ bb,
                                        const float* __restrict__ bnb,
                                        float* __restrict__ out0, float* __restrict__ out1, int n) {
    const float* in  = blockIdx.y ? in1 : in0;
    const float* W   = Wb  + (blockIdx.y ? 96 * 32 : 0);
    const float* b   = bb  + (blockIdx.y ? 32 : 0);
    const float* bn  = bnb + (blockIdx.y ? 128 : 0);
    float*       out = blockIdx.y ? out1 : out0;

    __shared__ float sW[96 * 32];
    __shared__ float sIn[32][97];
    __shared__ float sScale[32], sShift[32];
    const int t = threadIdx.x;  // 256

    for (int i = t; i < 96 * 32; i += 256) sW[i] = W[i];
    if (t < 32) {
        float gamma = bn[t], beta = bn[32 + t], mean = bn[64 + t], var = bn[96 + t];
        float sc = gamma * rsqrtf(var + 1e-5f);
        sScale[t] = sc;
        sShift[t] = beta + (b[t] - mean) * sc;
    }
    const int node0 = blockIdx.x * 32;
    for (int i = t; i < 32 * 96; i += 256) {
        int r = i / 96, k = i - r * 96;
        int gn = node0 + r;
        sIn[r][k] = (gn < n) ? in[(size_t)gn * 96 + k] : 0.f;
    }
    __syncthreads();

    const int c = t & 31, ng = t >> 5;
    float acc[4] = {0.f, 0.f, 0.f, 0.f};
    #pragma unroll 8
    for (int k = 0; k < 96; k++) {
        float wv = sW[k * 32 + c];
        #pragma unroll
        for (int r = 0; r < 4; r++) acc[r] = fmaf(sIn[ng * 4 + r][k], wv, acc[r]);
    }
    #pragma unroll
    for (int r = 0; r < 4; r++) {
        int gn = node0 + ng * 4 + r;
        if (gn < n) {
            float y = acc[r] * sScale[c] + sShift[c];
            out[(size_t)gn * 32 + c] = y > 0.f ? y : 0.f;
        }
    }
}

// ==================================================================================
extern "C" void kernel_launch(void* const* d_in, const int* in_sizes, int n_in,
                              void* d_out, int out_size) {
    const float* emb_user = (const float*)d_in[0];
    const float* emb_item = (const float*)d_in[1];
    const float* W1    = (const float*)d_in[2];
    const float* attn1 = (const float*)d_in[3];
    const float* res1  = (const float*)d_in[4];
    const float* bias1 = (const float*)d_in[5];
    const float* nnW1  = (const float*)d_in[6];
    const float* nnb1  = (const float*)d_in[7];
    const float* bn1   = (const float*)d_in[8];
    const float* W2    = (const float*)d_in[9];
    const float* attn2 = (const float*)d_in[10];
    const float* res2  = (const float*)d_in[11];
    const float* bias2 = (const float*)d_in[12];
    const float* nnW2  = (const float*)d_in[13];
    const float* nnb2  = (const float*)d_in[14];
    const float* bn2   = (const float*)d_in[15];
    const int* go_src   = (const int*)d_in[16];
    const int* go_dst   = (const int*)d_in[17];
    const int* back_src = (const int*)d_in[18];
    const int* back_dst = (const int*)d_in[19];
    const int E = in_sizes[16];
    const int N = NN;

    float *FS, *EL, *ER, *RES, *GU, *GI, *HU, *HI, *EX;
    int *DEG, *OFF, *CUR, *EIDX, *EDST, *BSUM;
    cudaGetSymbolAddress((void**)&FS,   g_FS);
    cudaGetSymbolAddress((void**)&EL,   g_EL);
    cudaGetSymbolAddress((void**)&ER,   g_ER);
    cudaGetSymbolAddress((void**)&RES,  g_RES);
    cudaGetSymbolAddress((void**)&GU,   g_GU);
    cudaGetSymbolAddress((void**)&GI,   g_GI);
    cudaGetSymbolAddress((void**)&HU,   g_HU);
    cudaGetSymbolAddress((void**)&HI,   g_HI);
    cudaGetSymbolAddress((void**)&EX,   g_EX);
    cudaGetSymbolAddress((void**)&DEG,  g_deg);
    cudaGetSymbolAddress((void**)&OFF,  g_off);
    cudaGetSymbolAddress((void**)&CUR,  g_cur);
    cudaGetSymbolAddress((void**)&EIDX, g_eidx);
    cudaGetSymbolAddress((void**)&EDST, g_edst);
    cudaGetSymbolAddress((void**)&BSUM, g_bsum);

    const int NB2 = (2 * N + 1023) / 1024;   // 196
    const int eb = (E + 255) / 256;

    // ---- CSR build (joint scan over both relations) ----
    zero_kernel<<<(2 * N + 255) / 256, 256>>>(DEG, 2 * N);
    count_dual_kernel<<<dim3(eb, 2), 256>>>(go_dst, back_dst, DEG, E);
    scan1_kernel<<<NB2, 1024>>>(DEG, OFF, BSUM, 2 * N);
    scan2_kernel<<<1, 256>>>(BSUM, NB2);
    scan3_copy_kernel<<<NB2, 1024>>>(OFF, BSUM, CUR, 2 * N);
    scatter_dual_kernel<<<dim3(eb, 2), 256>>>(go_src, go_dst, back_src, back_dst,
                                              CUR, EIDX, EDST, E);

    const int gemmBlocks = (N + 63) / 64;
    const int gatherBlocks = (N * 32 + 255) / 256;
    const int avBlocks = (N + 127) / 128;

    auto gat_pass = [&](const float* Xs, const float* Xd, int K,
                        const float* W, const float* al, const float* ar,
                        const float* rW, const float* bias,
                        int rel, float* gout) {
        if (K == 64) {
            gemm96_dual_kernel<64><<<dim3(gemmBlocks, 2), dim3(24, 8)>>>(Xs, W, FS, Xd, rW, RES, N);
            attnvec_dual_kernel<64><<<dim3(avBlocks, 2), 128>>>(Xs, Xd, W, al, ar, EL, ER, N);
        } else {
            gemm96_dual_kernel<32><<<dim3(gemmBlocks, 2), dim3(24, 8)>>>(Xs, W, FS, Xd, rW, RES, N);
            attnvec_dual_kernel<32><<<dim3(avBlocks, 2), 128>>>(Xs, Xd, W, al, ar, EL, ER, N);
        }
        edge_exp_kernel<<<eb, 256>>>(EIDX + rel * E, EDST + rel * E, EL, ER, EX + rel * E * 3, E);
        gat_gather_kernel<<<gatherBlocks, 256>>>(EIDX, EX, OFF, FS, RES, bias, gout,
                                                 N, rel * N, 2 * E);
    };

    // ---- layer 1 ----
    gat_pass(emb_user, emb_item, 64, W1, attn1, attn1 + 96, res1, bias1, 0, GI);
    gat_pass(emb_item, emb_user, 64, W1 + 64 * 96, attn1 + 192, attn1 + 288,
             res1 + 64 * 96, bias1 + 96, 1, GU);
    lin_bn_relu_dual_kernel<<<dim3((N + 31) / 32, 2), 256>>>(GU, GI, nnW1, nnb1, bn1, HU, HI, N);

    // ---- layer 2 ----
    gat_pass(HU, HI, 32, W2, attn2, attn2 + 96, res2, bias2, 0, GI);
    gat_pass(HI, HU, 32, W2 + 32 * 96, attn2 + 192, attn2 + 288,
             res2 + 32 * 96, bias2 + 96, 1, GU);

    float* out = (float*)d_out;
    lin_bn_relu_dual_kernel<<<dim3((N + 31) / 32, 2), 256>>>(GU, GI, nnW2, nnb2, bn2,
                                                             out, out + (size_t)N * 32, N);
}